// round 4
// baseline (speedup 1.0000x reference)
#include <cuda_runtime.h>
#include <math.h>

#define BB 16
#define SS 2048
#define TT 1024
#define EE 256
#define DD 256

// Scratch (static device globals: no allocation in kernel_launch)
__device__ __align__(16) float g_enc_proj[(size_t)BB * SS * DD];   // 33.5 MB
__device__ __align__(16) float g_context[(size_t)BB * TT * EE];    // 16.8 MB

// ---------------------------------------------------------------------------
// Kernel 1: enc_proj[b,s,:] = enc_states[b,s,:] @ W_enc   (M=B*S, K=E, N=D)
// 64x64 block tile, 256 threads, 4x4 per-thread microtile, K-tile 32.
// Row stride 68 floats: 16B-aligned float4 rows (68%4==0), bank-shifted per k.
// ---------------------------------------------------------------------------
__global__ __launch_bounds__(256, 1) void k_enc_proj(const float* __restrict__ A,
                                                     const float* __restrict__ W)
{
    __shared__ float Ast[32][68];   // transposed A tile [k][m]
    __shared__ float Bs[32][64];    // W tile [k][n]

    const int tid = threadIdx.x;
    const int tx = tid & 15, ty = tid >> 4;
    const int m0 = blockIdx.y * 64, n0 = blockIdx.x * 64;

    float acc[4][4];
#pragma unroll
    for (int i = 0; i < 4; ++i)
#pragma unroll
        for (int j = 0; j < 4; ++j) acc[i][j] = 0.f;

    for (int k0 = 0; k0 < EE; k0 += 32) {
#pragma unroll
        for (int it = 0; it < 2; ++it) {
            int f = tid + it * 256;
            int m = f >> 3, k4 = (f & 7) * 4;
            float4 v = *(const float4*)(A + (size_t)(m0 + m) * EE + k0 + k4);
            Ast[k4 + 0][m] = v.x; Ast[k4 + 1][m] = v.y;
            Ast[k4 + 2][m] = v.z; Ast[k4 + 3][m] = v.w;
        }
#pragma unroll
        for (int it = 0; it < 2; ++it) {
            int f = tid + it * 256;
            int k = f >> 4, n4 = (f & 15) * 4;
            *(float4*)&Bs[k][n4] = *(const float4*)(W + (size_t)(k0 + k) * DD + n0 + n4);
        }
        __syncthreads();
#pragma unroll
        for (int k = 0; k < 32; ++k) {
            float4 a = *(const float4*)&Ast[k][ty * 4];
            float4 b = *(const float4*)&Bs[k][tx * 4];
            float ar[4] = {a.x, a.y, a.z, a.w};
            float br[4] = {b.x, b.y, b.z, b.w};
#pragma unroll
            for (int i = 0; i < 4; ++i)
#pragma unroll
                for (int j = 0; j < 4; ++j) acc[i][j] += ar[i] * br[j];
        }
        __syncthreads();
    }
#pragma unroll
    for (int i = 0; i < 4; ++i) {
        float4 v = make_float4(acc[i][0], acc[i][1], acc[i][2], acc[i][3]);
        *(float4*)(g_enc_proj + (size_t)(m0 + ty * 4 + i) * DD + n0 + tx * 4) = v;
    }
}

// ---------------------------------------------------------------------------
// Kernel 2: fused flash-attention:
//   scores = dec_tile @ enc_proj^T (masked), online softmax over S,
//   context = softmax(scores) @ enc_states.  Writes normalized context.
// One CTA per (batch, 64-row T tile). 256 threads.
// ---------------------------------------------------------------------------
#define PADT 68
#define PADP 68
#define SDEC_F (256 * PADT)                 // 17408 floats
#define SMEM_ATTN_FLOATS (SDEC_F + SDEC_F + 64 * PADP + 64 + 64 + 64 + 64)
#define SMEM_ATTN_BYTES  (SMEM_ATTN_FLOATS * 4)

__global__ __launch_bounds__(256, 1) void k_attn(const float* __restrict__ encS,
                                                 const float* __restrict__ dec,
                                                 const int* __restrict__ mask)
{
    extern __shared__ float sm[];
    float* sDecT  = sm;                    // [256 k][68]  transposed dec tile
    float* sBuf   = sm + SDEC_F;           // chunk buffer: encP^T [256][68] OR enc [64][256]
    float* sP     = sm + 2 * SDEC_F;       // [64 t][68]   scores -> probabilities
    float* sM     = sP + 64 * PADP;        // running row max
    float* sL     = sM + 64;               // running row sum
    float* sScale = sL + 64;               // per-chunk rescale factor
    int*   sMask  = (int*)(sScale + 64);   // mask chunk

    const int tid = threadIdx.x;
    const int tx = tid & 15, ty = tid >> 4;
    const int b = blockIdx.y;
    const int t0 = blockIdx.x * 64;

    // Load dec tile (64 t x 256 k) transposed into smem
    const float* decBase = dec + ((size_t)b * TT + t0) * DD;
#pragma unroll
    for (int it = 0; it < 16; ++it) {
        int f = tid + it * 256;
        int t = f >> 6, k4 = (f & 63) * 4;
        float4 v = *(const float4*)(decBase + (size_t)t * DD + k4);
        sDecT[(k4 + 0) * PADT + t] = v.x;
        sDecT[(k4 + 1) * PADT + t] = v.y;
        sDecT[(k4 + 2) * PADT + t] = v.z;
        sDecT[(k4 + 3) * PADT + t] = v.w;
    }
    if (tid < 64) { sM[tid] = -INFINITY; sL[tid] = 0.f; }

    // context accumulator: rows ty*4+i, cols g*64 + tx*4 + j
    float acc[4][16];
#pragma unroll
    for (int i = 0; i < 4; ++i)
#pragma unroll
        for (int c = 0; c < 16; ++c) acc[i][c] = 0.f;

    for (int s0 = 0; s0 < SS; s0 += 64) {
        __syncthreads();   // protect sBuf / sP from previous iteration readers

        // Load enc_proj chunk (64 s x 256 k) transposed
        const float* epBase = g_enc_proj + ((size_t)b * SS + s0) * DD;
#pragma unroll
        for (int it = 0; it < 16; ++it) {
            int f = tid + it * 256;
            int s = f >> 6, k4 = (f & 63) * 4;
            float4 v = *(const float4*)(epBase + (size_t)s * DD + k4);
            sBuf[(k4 + 0) * PADT + s] = v.x;
            sBuf[(k4 + 1) * PADT + s] = v.y;
            sBuf[(k4 + 2) * PADT + s] = v.z;
            sBuf[(k4 + 3) * PADT + s] = v.w;
        }
        if (tid < 64) sMask[tid] = mask[(size_t)b * SS + s0 + tid];
        __syncthreads();

        // GEMM1: scores[64 t][64 s] = dec_tile @ encP_chunk^T  (K=256)
        float sc[4][4];
#pragma unroll
        for (int i = 0; i < 4; ++i)
#pragma unroll
            for (int j = 0; j < 4; ++j) sc[i][j] = 0.f;
#pragma unroll 16
        for (int k = 0; k < 256; ++k) {
            float4 a = *(const float4*)&sDecT[k * PADT + ty * 4];
            float4 bb = *(const float4*)&sBuf[k * PADT + tx * 4];
            float ar[4] = {a.x, a.y, a.z, a.w};
            float br[4] = {bb.x, bb.y, bb.z, bb.w};
#pragma unroll
            for (int i = 0; i < 4; ++i)
#pragma unroll
                for (int j = 0; j < 4; ++j) sc[i][j] += ar[i] * br[j];
        }

        // Apply mask, write to sP
#pragma unroll
        for (int j = 0; j < 4; ++j) {
            bool mj = sMask[tx * 4 + j] != 0;
#pragma unroll
            for (int i = 0; i < 4; ++i)
                sP[(ty * 4 + i) * PADP + tx * 4 + j] = mj ? sc[i][j] : -INFINITY;
        }
        __syncthreads();

        // Online softmax: 4 lanes per row, 16 cols each
        {
            int r = tid >> 2, q = tid & 3;
            float* row = sP + r * PADP + q * 16;
            float v[16];
            float mloc = -INFINITY;
#pragma unroll
            for (int j = 0; j < 16; ++j) { v[j] = row[j]; mloc = fmaxf(mloc, v[j]); }
            mloc = fmaxf(mloc, __shfl_xor_sync(0xffffffffu, mloc, 1));
            mloc = fmaxf(mloc, __shfl_xor_sync(0xffffffffu, mloc, 2));
            float mold = sM[r];
            float mnew = fmaxf(mold, mloc);
            float scale = 1.f, sum = 0.f;
            if (mnew == -INFINITY) {     // all-masked so far: keep everything zero
#pragma unroll
                for (int j = 0; j < 16; ++j) v[j] = 0.f;
            } else {
                scale = __expf(mold - mnew);   // mold=-inf -> 0
#pragma unroll
                for (int j = 0; j < 16; ++j) { v[j] = __expf(v[j] - mnew); sum += v[j]; }
            }
            sum += __shfl_xor_sync(0xffffffffu, sum, 1);
            sum += __shfl_xor_sync(0xffffffffu, sum, 2);
#pragma unroll
            for (int j = 0; j < 16; ++j) row[j] = v[j];
            if (q == 0) { sM[r] = mnew; sL[r] = sL[r] * scale + sum; sScale[r] = scale; }
        }
        __syncthreads();

        // Load enc_states chunk (64 s x 256 e), natural layout
        const float* eBase = encS + ((size_t)b * SS + s0) * EE;
#pragma unroll
        for (int it = 0; it < 16; ++it) {
            int f = tid + it * 256;
            int s = f >> 6, e4 = (f & 63) * 4;
            *(float4*)&sBuf[s * EE + e4] = *(const float4*)(eBase + (size_t)s * EE + e4);
        }
        __syncthreads();

        // Rescale accumulator, then GEMM2: acc += P_chunk @ enc_chunk
        float rs[4];
#pragma unroll
        for (int i = 0; i < 4; ++i) rs[i] = sScale[ty * 4 + i];
#pragma unroll
        for (int i = 0; i < 4; ++i)
#pragma unroll
            for (int c = 0; c < 16; ++c) acc[i][c] *= rs[i];

#pragma unroll 8
        for (int s = 0; s < 64; ++s) {
            float pv[4];
#pragma unroll
            for (int i = 0; i < 4; ++i) pv[i] = sP[(ty * 4 + i) * PADP + s];
#pragma unroll
            for (int g = 0; g < 4; ++g) {
                float4 e = *(const float4*)&sBuf[s * EE + g * 64 + tx * 4];
#pragma unroll
                for (int i = 0; i < 4; ++i) {
                    acc[i][g * 4 + 0] += pv[i] * e.x;
                    acc[i][g * 4 + 1] += pv[i] * e.y;
                    acc[i][g * 4 + 2] += pv[i] * e.z;
                    acc[i][g * 4 + 3] += pv[i] * e.w;
                }
            }
        }
    }

    // Normalize + write context
    float inv[4];
#pragma unroll
    for (int i = 0; i < 4; ++i) inv[i] = 1.f / sL[ty * 4 + i];
    float* cBase = g_context + ((size_t)b * TT + t0) * EE;
#pragma unroll
    for (int i = 0; i < 4; ++i) {
#pragma unroll
        for (int g = 0; g < 4; ++g) {
            float4 v = make_float4(acc[i][g * 4 + 0] * inv[i], acc[i][g * 4 + 1] * inv[i],
                                   acc[i][g * 4 + 2] * inv[i], acc[i][g * 4 + 3] * inv[i]);
            *(float4*)(cBase + (size_t)(ty * 4 + i) * EE + g * 64 + tx * 4) = v;
        }
    }
}

// ---------------------------------------------------------------------------
// Kernel 3: out = tanh( [context, dec] @ W_fin )   (M=B*T, K=512, N=D)
// Split-source A: k<256 from g_context, k>=256 from dec_states.
// ---------------------------------------------------------------------------
__global__ __launch_bounds__(256, 1) void k_final(const float* __restrict__ dec,
                                                  const float* __restrict__ Wfin,
                                                  float* __restrict__ out)
{
    __shared__ float Ast[32][68];
    __shared__ float Bs[32][64];

    const int tid = threadIdx.x;
    const int tx = tid & 15, ty = tid >> 4;
    const int m0 = blockIdx.y * 64, n0 = blockIdx.x * 64;

    float acc[4][4];
#pragma unroll
    for (int i = 0; i < 4; ++i)
#pragma unroll
        for (int j = 0; j < 4; ++j) acc[i][j] = 0.f;

    for (int kt = 0; kt < 16; ++kt) {
        int k0 = kt * 32;
        const float* src = (k0 < 256) ? g_context : dec;
        int koff = (k0 < 256) ? k0 : (k0 - 256);
#pragma unroll
        for (int it = 0; it < 2; ++it) {
            int f = tid + it * 256;
            int m = f >> 3, k4 = (f & 7) * 4;
            float4 v = *(const float4*)(src + (size_t)(m0 + m) * 256 + koff + k4);
            Ast[k4 + 0][m] = v.x; Ast[k4 + 1][m] = v.y;
            Ast[k4 + 2][m] = v.z; Ast[k4 + 3][m] = v.w;
        }
#pragma unroll
        for (int it = 0; it < 2; ++it) {
            int f = tid + it * 256;
            int k = f >> 4, n4 = (f & 15) * 4;
            *(float4*)&Bs[k][n4] = *(const float4*)(Wfin + (size_t)(k0 + k) * DD + n0 + n4);
        }
        __syncthreads();
#pragma unroll
        for (int k = 0; k < 32; ++k) {
            float4 a = *(const float4*)&Ast[k][ty * 4];
            float4 b = *(const float4*)&Bs[k][tx * 4];
            float ar[4] = {a.x, a.y, a.z, a.w};
            float br[4] = {b.x, b.y, b.z, b.w};
#pragma unroll
            for (int i = 0; i < 4; ++i)
#pragma unroll
                for (int j = 0; j < 4; ++j) acc[i][j] += ar[i] * br[j];
        }
        __syncthreads();
    }
#pragma unroll
    for (int i = 0; i < 4; ++i) {
        float4 v = make_float4(tanhf(acc[i][0]), tanhf(acc[i][1]),
                               tanhf(acc[i][2]), tanhf(acc[i][3]));
        *(float4*)(out + (size_t)(m0 + ty * 4 + i) * DD + n0 + tx * 4) = v;
    }
}

// ---------------------------------------------------------------------------
extern "C" void kernel_launch(void* const* d_in, const int* in_sizes, int n_in,
                              void* d_out, int out_size)
{
    const float* enc  = (const float*)d_in[0];   // (B,S,E)
    const float* dec  = (const float*)d_in[1];   // (B,T,D)
    const int*   mask = (const int*)d_in[2];     // (B,S) bool -> int32
    const float* Wenc = (const float*)d_in[3];   // (E,D)
    const float* Wfin = (const float*)d_in[4];   // (E+D,D)
    float* out = (float*)d_out;                  // (B,T,D)

    cudaFuncSetAttribute(k_attn, cudaFuncAttributeMaxDynamicSharedMemorySize, SMEM_ATTN_BYTES);

    k_enc_proj<<<dim3(DD / 64, (BB * SS) / 64), 256>>>(enc, Wenc);
    k_attn<<<dim3(TT / 64, BB), 256, SMEM_ATTN_BYTES>>>(enc, dec, mask);
    k_final<<<dim3(DD / 64, (BB * TT) / 64), 256>>>(dec, Wfin, out);
}

// round 5
// speedup vs baseline: 1.1961x; 1.1961x over previous
#include <cuda_runtime.h>
#include <math.h>

#define BB 16
#define SS 2048
#define TT 1024
#define EE 256
#define DD 256

typedef unsigned long long u64;

// Scratch (static device globals: no allocation in kernel_launch)
__device__ __align__(16) float g_dec_proj[(size_t)BB * TT * EE];   // 16.8 MB
__device__ __align__(16) float g_context[(size_t)BB * TT * EE];    // 16.8 MB

// ---- packed f32x2 helpers ------------------------------------------------
__device__ __forceinline__ u64 dup2(float x) {
    u64 r; asm("mov.b64 %0, {%1, %1};" : "=l"(r) : "f"(x)); return r;
}
__device__ __forceinline__ void fma2(u64& d, u64 a, u64 b) {
    asm("fma.rn.f32x2 %0, %1, %2, %0;" : "+l"(d) : "l"(a), "l"(b));
}
__device__ __forceinline__ void mul2(u64& d, u64 a) {
    asm("mul.rn.f32x2 %0, %0, %1;" : "+l"(d) : "l"(a));
}
__device__ __forceinline__ float2 unpk(u64 v) {
    float a, b; asm("mov.b64 {%0, %1}, %2;" : "=f"(a), "=f"(b) : "l"(v));
    return make_float2(a, b);
}

// ---------------------------------------------------------------------------
// Kernel 1: dec_proj[b,t,:] = dec[b,t,:] @ W_enc^T   (M=B*T, K=D, N=E)
//   (scores = dec @ (enc W)^T == (dec W^T) @ enc^T — reassociated)
// 64x64 tile, 256 threads, 4x4 microtile via f32x2 pairs, K-tile 32.
// ---------------------------------------------------------------------------
__global__ __launch_bounds__(256) void k_dec_proj(const float* __restrict__ dec,
                                                  const float* __restrict__ W)
{
    __shared__ float Ast[32][68];   // transposed dec tile [d][t]
    __shared__ float Bs[32][68];    // W^T tile [d][e]

    const int tid = threadIdx.x;
    const int tx = tid & 15, ty = tid >> 4;
    const int m0 = blockIdx.y * 64, n0 = blockIdx.x * 64;

    u64 acc[2][4];
#pragma unroll
    for (int p = 0; p < 2; ++p)
#pragma unroll
        for (int j = 0; j < 4; ++j) acc[p][j] = 0ull;

    for (int k0 = 0; k0 < DD; k0 += 32) {
#pragma unroll
        for (int it = 0; it < 2; ++it) {
            int f = tid + it * 256;
            int m = f >> 3, k4 = (f & 7) * 4;
            float4 v = *(const float4*)(dec + (size_t)(m0 + m) * DD + k0 + k4);
            Ast[k4 + 0][m] = v.x; Ast[k4 + 1][m] = v.y;
            Ast[k4 + 2][m] = v.z; Ast[k4 + 3][m] = v.w;
        }
#pragma unroll
        for (int it = 0; it < 2; ++it) {
            int f = tid + it * 256;
            int e = f >> 3, k4 = (f & 7) * 4;
            float4 v = *(const float4*)(W + (size_t)(n0 + e) * DD + k0 + k4);
            Bs[k4 + 0][e] = v.x; Bs[k4 + 1][e] = v.y;
            Bs[k4 + 2][e] = v.z; Bs[k4 + 3][e] = v.w;
        }
        __syncthreads();
#pragma unroll
        for (int k = 0; k < 32; ++k) {
            ulonglong2 a2 = *(const ulonglong2*)&Ast[k][ty * 4];
            float4 b = *(const float4*)&Bs[k][tx * 4];
            u64 b0 = dup2(b.x), b1 = dup2(b.y), b2 = dup2(b.z), b3 = dup2(b.w);
            fma2(acc[0][0], a2.x, b0); fma2(acc[1][0], a2.y, b0);
            fma2(acc[0][1], a2.x, b1); fma2(acc[1][1], a2.y, b1);
            fma2(acc[0][2], a2.x, b2); fma2(acc[1][2], a2.y, b2);
            fma2(acc[0][3], a2.x, b3); fma2(acc[1][3], a2.y, b3);
        }
        __syncthreads();
    }
    float2 u[2][4];
#pragma unroll
    for (int p = 0; p < 2; ++p)
#pragma unroll
        for (int j = 0; j < 4; ++j) u[p][j] = unpk(acc[p][j]);
    float* o = g_dec_proj + (size_t)(m0 + ty * 4) * EE + n0 + tx * 4;
    *(float4*)(o + 0 * EE) = make_float4(u[0][0].x, u[0][1].x, u[0][2].x, u[0][3].x);
    *(float4*)(o + 1 * EE) = make_float4(u[0][0].y, u[0][1].y, u[0][2].y, u[0][3].y);
    *(float4*)(o + 2 * EE) = make_float4(u[1][0].x, u[1][1].x, u[1][2].x, u[1][3].x);
    *(float4*)(o + 3 * EE) = make_float4(u[1][0].y, u[1][1].y, u[1][2].y, u[1][3].y);
}

// ---------------------------------------------------------------------------
// Kernel 2: fused flash-attention.
//   scores = dec_proj_tile @ enc_chunk^T (masked), online softmax over S,
//   context += softmax @ enc_chunk.  Single enc load feeds BOTH GEMMs.
// Transposed tiles stored at stride 64 with XOR swizzle  col ^ (e & 60):
//   float4 reads stay 16B-aligned & conflict-free; scatter STS 4-way max.
// ---------------------------------------------------------------------------
#define PADP 68
#define SMEM_ATTN_FLOATS (16384 + 16384 + 16384 + 64 * PADP + 64 + 64 + 64 + 64)
#define SMEM_ATTN_BYTES  (SMEM_ATTN_FLOATS * 4)

__global__ __launch_bounds__(256, 1) void k_attn(const float* __restrict__ encS,
                                                 const int* __restrict__ mask)
{
    extern __shared__ float sm[];
    float* sDecPT = sm;                    // [256 e][64 t] swizzled
    float* sEncT  = sm + 16384;            // [256 e][64 s] swizzled
    float* sEnc   = sm + 32768;            // [64 s][256 e] natural
    float* sP     = sm + 49152;            // [64 t][68]
    float* sM     = sP + 64 * PADP;
    float* sL     = sM + 64;
    float* sScale = sL + 64;
    int*   sMask  = (int*)(sScale + 64);

    const int tid = threadIdx.x;
    const int tx = tid & 15, ty = tid >> 4;
    const int b = blockIdx.y;
    const int t0 = blockIdx.x * 64;

    // Load dec_proj tile (64 t x 256 e) transposed+swizzled
    const float* dpBase = g_dec_proj + ((size_t)b * TT + t0) * EE;
#pragma unroll
    for (int it = 0; it < 16; ++it) {
        int f = tid + it * 256;
        int t = f >> 6, m = f & 63;
        int e4 = m * 4, swz = (m & 15) * 4;
        float4 v = *(const float4*)(dpBase + (size_t)t * EE + e4);
        int tc = t ^ swz;
        sDecPT[(e4 + 0) * 64 + tc] = v.x;
        sDecPT[(e4 + 1) * 64 + tc] = v.y;
        sDecPT[(e4 + 2) * 64 + tc] = v.z;
        sDecPT[(e4 + 3) * 64 + tc] = v.w;
    }
    if (tid < 64) { sM[tid] = -INFINITY; sL[tid] = 0.f; }

    u64 acc[4][8];   // context: rows ty*4+i, col pairs (g*4+{0,1}),(g*4+{2,3})
#pragma unroll
    for (int i = 0; i < 4; ++i)
#pragma unroll
        for (int c = 0; c < 8; ++c) acc[i][c] = 0ull;

    for (int s0 = 0; s0 < SS; s0 += 64) {
        __syncthreads();   // protect sEnc/sEncT/sP from previous-iter readers

        // Single enc chunk load -> natural + transposed-swizzled copies
        const float* eBase = encS + ((size_t)b * SS + s0) * EE;
#pragma unroll
        for (int it = 0; it < 16; ++it) {
            int f = tid + it * 256;
            int s = f >> 6, m = f & 63;
            int e4 = m * 4, swz = (m & 15) * 4;
            float4 v = *(const float4*)(eBase + (size_t)s * EE + e4);
            *(float4*)&sEnc[s * EE + e4] = v;
            int scc = s ^ swz;
            sEncT[(e4 + 0) * 64 + scc] = v.x;
            sEncT[(e4 + 1) * 64 + scc] = v.y;
            sEncT[(e4 + 2) * 64 + scc] = v.z;
            sEncT[(e4 + 3) * 64 + scc] = v.w;
        }
        if (tid < 64) sMask[tid] = mask[(size_t)b * SS + s0 + tid];
        __syncthreads();

        // GEMM1: scores[64 t][64 s] = decP_tile @ enc_chunk^T  (K=E=256)
        u64 sc2[2][4];
#pragma unroll
        for (int p = 0; p < 2; ++p)
#pragma unroll
            for (int j = 0; j < 4; ++j) sc2[p][j] = 0ull;
#pragma unroll 16
        for (int e = 0; e < 256; ++e) {
            int swz = e & 60;
            ulonglong2 a2 = *(const ulonglong2*)&sDecPT[e * 64 + ((ty * 4) ^ swz)];
            float4 b4 = *(const float4*)&sEncT[e * 64 + ((tx * 4) ^ swz)];
            u64 b0 = dup2(b4.x), b1 = dup2(b4.y), b2 = dup2(b4.z), b3 = dup2(b4.w);
            fma2(sc2[0][0], a2.x, b0); fma2(sc2[1][0], a2.y, b0);
            fma2(sc2[0][1], a2.x, b1); fma2(sc2[1][1], a2.y, b1);
            fma2(sc2[0][2], a2.x, b2); fma2(sc2[1][2], a2.y, b2);
            fma2(sc2[0][3], a2.x, b3); fma2(sc2[1][3], a2.y, b3);
        }
        float sc[4][4];
#pragma unroll
        for (int j = 0; j < 4; ++j) {
            float2 lo = unpk(sc2[0][j]), hi = unpk(sc2[1][j]);
            sc[0][j] = lo.x; sc[1][j] = lo.y; sc[2][j] = hi.x; sc[3][j] = hi.y;
        }

        // Mask + stage scores
#pragma unroll
        for (int j = 0; j < 4; ++j) {
            bool mj = sMask[tx * 4 + j] != 0;
#pragma unroll
            for (int i = 0; i < 4; ++i)
                sP[(ty * 4 + i) * PADP + tx * 4 + j] = mj ? sc[i][j] : -INFINITY;
        }
        __syncthreads();

        // Online softmax: 4 lanes per row, 16 cols each
        {
            int r = tid >> 2, q = tid & 3;
            float* row = sP + r * PADP + q * 16;
            float v[16];
            float mloc = -INFINITY;
#pragma unroll
            for (int j = 0; j < 16; ++j) { v[j] = row[j]; mloc = fmaxf(mloc, v[j]); }
            mloc = fmaxf(mloc, __shfl_xor_sync(0xffffffffu, mloc, 1));
            mloc = fmaxf(mloc, __shfl_xor_sync(0xffffffffu, mloc, 2));
            float mold = sM[r];
            float mnew = fmaxf(mold, mloc);
            float scale = 1.f, sum = 0.f;
            if (mnew == -INFINITY) {
#pragma unroll
                for (int j = 0; j < 16; ++j) v[j] = 0.f;
            } else {
                scale = __expf(mold - mnew);
#pragma unroll
                for (int j = 0; j < 16; ++j) { v[j] = __expf(v[j] - mnew); sum += v[j]; }
            }
            sum += __shfl_xor_sync(0xffffffffu, sum, 1);
            sum += __shfl_xor_sync(0xffffffffu, sum, 2);
#pragma unroll
            for (int j = 0; j < 16; ++j) row[j] = v[j];
            if (q == 0) { sM[r] = mnew; sL[r] = sL[r] * scale + sum; sScale[r] = scale; }
        }
        __syncthreads();

        // Rescale running context, then GEMM2: acc += P_chunk @ enc_chunk
        {
            u64 rs0 = dup2(sScale[ty * 4 + 0]);
            u64 rs1 = dup2(sScale[ty * 4 + 1]);
            u64 rs2 = dup2(sScale[ty * 4 + 2]);
            u64 rs3 = dup2(sScale[ty * 4 + 3]);
#pragma unroll
            for (int c = 0; c < 8; ++c) {
                mul2(acc[0][c], rs0); mul2(acc[1][c], rs1);
                mul2(acc[2][c], rs2); mul2(acc[3][c], rs3);
            }
        }
#pragma unroll 4
        for (int s = 0; s < 64; ++s) {
            u64 pd[4];
#pragma unroll
            for (int i = 0; i < 4; ++i) pd[i] = dup2(sP[(ty * 4 + i) * PADP + s]);
#pragma unroll
            for (int g = 0; g < 4; ++g) {
                ulonglong2 ee = *(const ulonglong2*)&sEnc[s * EE + g * 64 + tx * 4];
#pragma unroll
                for (int i = 0; i < 4; ++i) {
                    fma2(acc[i][g * 2 + 0], pd[i], ee.x);
                    fma2(acc[i][g * 2 + 1], pd[i], ee.y);
                }
            }
        }
    }

    // Normalize + write context
    float inv[4];
#pragma unroll
    for (int i = 0; i < 4; ++i) inv[i] = 1.f / sL[ty * 4 + i];
    float* cBase = g_context + ((size_t)b * TT + t0) * EE;
#pragma unroll
    for (int i = 0; i < 4; ++i) {
#pragma unroll
        for (int g = 0; g < 4; ++g) {
            float2 lo = unpk(acc[i][g * 2 + 0]);
            float2 hi = unpk(acc[i][g * 2 + 1]);
            float4 v = make_float4(lo.x * inv[i], lo.y * inv[i], hi.x * inv[i], hi.y * inv[i]);
            *(float4*)(cBase + (size_t)(ty * 4 + i) * EE + g * 64 + tx * 4) = v;
        }
    }
}

// ---------------------------------------------------------------------------
// Kernel 3: out = tanh( [context, dec] @ W_fin )   (M=B*T, K=512, N=D)
// ---------------------------------------------------------------------------
__global__ __launch_bounds__(256) void k_final(const float* __restrict__ dec,
                                               const float* __restrict__ Wfin,
                                               float* __restrict__ out)
{
    __shared__ float Ast[32][68];
    __shared__ float Bs[32][68];

    const int tid = threadIdx.x;
    const int tx = tid & 15, ty = tid >> 4;
    const int m0 = blockIdx.y * 64, n0 = blockIdx.x * 64;

    u64 acc[2][4];
#pragma unroll
    for (int p = 0; p < 2; ++p)
#pragma unroll
        for (int j = 0; j < 4; ++j) acc[p][j] = 0ull;

    for (int kt = 0; kt < 16; ++kt) {
        int k0 = kt * 32;
        const float* src = (k0 < 256) ? g_context : dec;
        int koff = (k0 < 256) ? k0 : (k0 - 256);
#pragma unroll
        for (int it = 0; it < 2; ++it) {
            int f = tid + it * 256;
            int m = f >> 3, k4 = (f & 7) * 4;
            float4 v = *(const float4*)(src + (size_t)(m0 + m) * 256 + koff + k4);
            Ast[k4 + 0][m] = v.x; Ast[k4 + 1][m] = v.y;
            Ast[k4 + 2][m] = v.z; Ast[k4 + 3][m] = v.w;
        }
#pragma unroll
        for (int it = 0; it < 2; ++it) {
            int f = tid + it * 256;
            int k = f >> 4, n4 = (f & 15) * 4;
            *(float4*)&Bs[k][n4] = *(const float4*)(Wfin + (size_t)(k0 + k) * DD + n0 + n4);
        }
        __syncthreads();
#pragma unroll
        for (int k = 0; k < 32; ++k) {
            ulonglong2 a2 = *(const ulonglong2*)&Ast[k][ty * 4];
            float4 b = *(const float4*)&Bs[k][tx * 4];
            u64 b0 = dup2(b.x), b1 = dup2(b.y), b2 = dup2(b.z), b3 = dup2(b.w);
            fma2(acc[0][0], a2.x, b0); fma2(acc[1][0], a2.y, b0);
            fma2(acc[0][1], a2.x, b1); fma2(acc[1][1], a2.y, b1);
            fma2(acc[0][2], a2.x, b2); fma2(acc[1][2], a2.y, b2);
            fma2(acc[0][3], a2.x, b3); fma2(acc[1][3], a2.y, b3);
        }
        __syncthreads();
    }
    float2 u[2][4];
#pragma unroll
    for (int p = 0; p < 2; ++p)
#pragma unroll
        for (int j = 0; j < 4; ++j) u[p][j] = unpk(acc[p][j]);
    float* o = out + (size_t)(m0 + ty * 4) * DD + n0 + tx * 4;
    *(float4*)(o + 0 * DD) = make_float4(tanhf(u[0][0].x), tanhf(u[0][1].x), tanhf(u[0][2].x), tanhf(u[0][3].x));
    *(float4*)(o + 1 * DD) = make_float4(tanhf(u[0][0].y), tanhf(u[0][1].y), tanhf(u[0][2].y), tanhf(u[0][3].y));
    *(float4*)(o + 2 * DD) = make_float4(tanhf(u[1][0].x), tanhf(u[1][1].x), tanhf(u[1][2].x), tanhf(u[1][3].x));
    *(float4*)(o + 3 * DD) = make_float4(tanhf(u[1][0].y), tanhf(u[1][1].y), tanhf(u[1][2].y), tanhf(u[1][3].y));
}

// ---------------------------------------------------------------------------
extern "C" void kernel_launch(void* const* d_in, const int* in_sizes, int n_in,
                              void* d_out, int out_size)
{
    const float* enc  = (const float*)d_in[0];   // (B,S,E)
    const float* dec  = (const float*)d_in[1];   // (B,T,D)
    const int*   mask = (const int*)d_in[2];     // (B,S) bool -> int32
    const float* Wenc = (const float*)d_in[3];   // (E,D)
    const float* Wfin = (const float*)d_in[4];   // (E+D,D)
    float* out = (float*)d_out;                  // (B,T,D)

    cudaFuncSetAttribute(k_attn, cudaFuncAttributeMaxDynamicSharedMemorySize, SMEM_ATTN_BYTES);

    k_dec_proj<<<dim3(EE / 64, (BB * TT) / 64), 256>>>(dec, Wenc);
    k_attn<<<dim3(TT / 64, BB), 256, SMEM_ATTN_BYTES>>>(enc, mask);
    k_final<<<dim3(DD / 64, (BB * TT) / 64), 256>>>(dec, Wfin, out);
}